// round 2
// baseline (speedup 1.0000x reference)
#include <cuda_runtime.h>

typedef unsigned long long ull;

#define NB 4
#define NN 256
#define DD 128
#define HH 128
#define TI 16
#define TJ 8
#define KC 32

// Per-node halves of the first linear layer.
// g_A[b*N+i, h]  = b1[h] + sum_k x[i,k]*W1[k,h]
// g_Bv[b*N+j, h] =         sum_k x[j,k]*W1[128+k,h]
__device__ float g_A[NB * NN * HH];
__device__ float g_Bv[NB * NN * HH];

// ---------- f32x2 helpers ----------
__device__ __forceinline__ ull pack2(float lo, float hi) {
    ull r; asm("mov.b64 %0, {%1,%2};" : "=l"(r) : "f"(lo), "f"(hi)); return r;
}
__device__ __forceinline__ ull dup2(float x) { return pack2(x, x); }
__device__ __forceinline__ void unpack2(ull v, float& lo, float& hi) {
    asm("mov.b64 {%0,%1}, %2;" : "=f"(lo), "=f"(hi) : "l"(v));
}
__device__ __forceinline__ ull ffma2(ull a, ull b, ull c) {
    ull d; asm("fma.rn.f32x2 %0, %1, %2, %3;" : "=l"(d) : "l"(a), "l"(b), "l"(c)); return d;
}
__device__ __forceinline__ ull fmul2(ull a, ull b) {
    ull d; asm("mul.rn.f32x2 %0, %1, %2;" : "=l"(d) : "l"(a), "l"(b)); return d;
}
__device__ __forceinline__ ull fadd2(ull a, ull b) {
    ull d; asm("add.rn.f32x2 %0, %1, %2;" : "=l"(d) : "l"(a), "l"(b)); return d;
}

__device__ __forceinline__ float clip20(float x) { return fminf(fmaxf(x, -20.0f), 20.0f); }
__device__ __forceinline__ float sigm(float x)  { return 1.0f / (1.0f + __expf(-x)); }

// ---------- Kernel 1: per-node precompute ----------
__global__ void precompute_ab(const float* __restrict__ X,
                              const float* __restrict__ W1,
                              const float* __restrict__ b1) {
    __shared__ float Xs[8 * DD];
    int r0 = blockIdx.x * 8;      // rows over flattened b*N (1024 rows)
    int h  = threadIdx.x;         // 128 threads = hidden index

    for (int e = h; e < 8 * DD / 4; e += 128)
        ((float4*)Xs)[e] = ((const float4*)(X + r0 * DD))[e];
    __syncthreads();

    float accA[8], accB[8];
#pragma unroll
    for (int r = 0; r < 8; r++) { accA[r] = 0.f; accB[r] = 0.f; }

    for (int k = 0; k < DD; k++) {
        float wa = W1[k * HH + h];
        float wb = W1[(DD + k) * HH + h];
#pragma unroll
        for (int r = 0; r < 8; r++) {
            float x = Xs[r * DD + k];
            accA[r] += x * wa;
            accB[r] += x * wb;
        }
    }
    float bb = b1[h];
#pragma unroll
    for (int r = 0; r < 8; r++) {
        g_A[(r0 + r) * HH + h]  = accA[r] + bb;
        g_Bv[(r0 + r) * HH + h] = accB[r];
    }
}

// ---------- Kernel 2: fused pairwise MLP ----------
struct SmemMain {
    float his[TI * DD];   // 16 i-rows
    float hjT[DD * TJ];   // 8 j-rows, transposed [k][jj]
    float Wc[KC * HH];    // |hi-hj| weight chunk
    float Wd[KC * HH];    // hi*hj   weight chunk
};
struct SmemEpi {
    float Ai[TI * HH];
    float Bi[TI * HH];
    float Aj[TJ * HH];
    float Bj[TJ * HH];
    float red[2 * TI * TJ * 16];
};
union SmemU { SmemMain m; SmemEpi e; };

__global__ void __launch_bounds__(256)
pair_mlp_kernel(const float* __restrict__ X,
                const float* __restrict__ base,
                const float* __restrict__ comp,
                const float* __restrict__ W1,
                const float* __restrict__ W2,
                const float* __restrict__ b2,
                float* __restrict__ out) {
    int jt = blockIdx.x, it = blockIdx.y, b = blockIdx.z;
    if (jt < 2 * it) return;   // tile strictly below diagonal band -> partner covers it
    int i0 = it * TI, j0 = jt * TJ;
    int tid = threadIdx.x;
    int hg = tid & 15;         // h-group: h in {hg*4..+3} U {64+hg*4..+3}
    int mg = tid >> 4;         // ii = mg; this thread does all 8 jj

    __shared__ __align__(16) SmemU sm;
    __shared__ __align__(16) float Wsc[4 * HH];  // W1 rows 512..515
    __shared__ __align__(16) float W2s[HH];

    const float* Xb = X + b * NN * DD;

    // stage: his, hjT (transposed), scalar weights, W2, chunk 0 of Wc/Wd
    {
        const float4* src = (const float4*)(Xb + i0 * DD);
        float4* dst = (float4*)sm.m.his;
        for (int e = tid; e < TI * DD / 4; e += 256) dst[e] = src[e];

        for (int e = tid; e < TJ * DD / 4; e += 256) {
            int jj = e >> 5;
            int k  = (e & 31) * 4;
            float4 v = *(const float4*)(Xb + (j0 + jj) * DD + k);
            sm.m.hjT[(k + 0) * TJ + jj] = v.x;
            sm.m.hjT[(k + 1) * TJ + jj] = v.y;
            sm.m.hjT[(k + 2) * TJ + jj] = v.z;
            sm.m.hjT[(k + 3) * TJ + jj] = v.w;
        }
        for (int e = tid; e < 4 * HH / 4; e += 256)
            ((float4*)Wsc)[e] = ((const float4*)(W1 + 512 * HH))[e];
        if (tid < HH / 4) ((float4*)W2s)[tid] = ((const float4*)W2)[tid];

        const float4* wcsrc = (const float4*)(W1 + 256 * HH);
        const float4* wdsrc = (const float4*)(W1 + 384 * HH);
        float4* wcd = (float4*)sm.m.Wc;
        float4* wdd = (float4*)sm.m.Wd;
        for (int e = tid; e < KC * HH / 4; e += 256) { wcd[e] = wcsrc[e]; wdd[e] = wdsrc[e]; }
    }
    __syncthreads();

    // acc[pp][h] : f32x2 over jj-pair (2pp, 2pp+1)
    ull acc[4][8];
#pragma unroll
    for (int p = 0; p < 4; p++)
#pragma unroll
        for (int h = 0; h < 8; h++) acc[p][h] = 0ULL;

    const float* hisP = sm.m.his + mg * DD;

    for (int c = 0; c < DD / KC; c++) {
        const float* hp = hisP + c * KC;
        const ulonglong2* hjp = (const ulonglong2*)sm.m.hjT + c * KC * 2;
#pragma unroll 8
        for (int kk = 0; kk < KC; kk++) {
            ull hi2 = dup2(hp[kk]);
            ulonglong2 ha = hjp[kk * 2];
            ulonglong2 hb = hjp[kk * 2 + 1];
            ull hj2[4] = { ha.x, ha.y, hb.x, hb.y };
            ull p2[4], a2[4];
#pragma unroll
            for (int pp = 0; pp < 4; pp++) {
                p2[pp] = fmul2(hi2, hj2[pp]);                          // hi*hj
                ull d2 = fadd2(hi2, hj2[pp] ^ 0x8000000080000000ULL);  // hi-hj
                a2[pp] = d2 & 0x7FFFFFFF7FFFFFFFULL;                   // |hi-hj|
            }
            const float* wcp = sm.m.Wc + kk * HH + hg * 4;
            const float* wdp = sm.m.Wd + kk * HH + hg * 4;
            float4 wcl = *(const float4*)wcp;
            float4 wcu = *(const float4*)(wcp + 64);
            float4 wdl = *(const float4*)wdp;
            float4 wdu = *(const float4*)(wdp + 64);
            float wc[8] = { wcl.x, wcl.y, wcl.z, wcl.w, wcu.x, wcu.y, wcu.z, wcu.w };
            float wd[8] = { wdl.x, wdl.y, wdl.z, wdl.w, wdu.x, wdu.y, wdu.z, wdu.w };
#pragma unroll
            for (int h = 0; h < 8; h++) {
                ull wc2 = dup2(wc[h]);
                ull wd2 = dup2(wd[h]);
#pragma unroll
                for (int pp = 0; pp < 4; pp++) {
                    acc[pp][h] = ffma2(a2[pp], wc2, acc[pp][h]);
                    acc[pp][h] = ffma2(p2[pp], wd2, acc[pp][h]);
                }
            }
        }
        __syncthreads();
        if (c + 1 < DD / KC) {
            const float4* wcsrc = (const float4*)(W1 + (256 + (c + 1) * KC) * HH);
            const float4* wdsrc = (const float4*)(W1 + (384 + (c + 1) * KC) * HH);
            float4* wcd = (float4*)sm.m.Wc;
            float4* wdd = (float4*)sm.m.Wd;
            for (int e = tid; e < KC * HH / 4; e += 256) { wcd[e] = wcsrc[e]; wdd[e] = wdsrc[e]; }
            __syncthreads();
        }
    }

    // epilogue: stage per-node A/B rows (union overlay is safe after the last sync)
    {
        const float4* asrc  = (const float4*)(g_A  + (b * NN + i0) * HH);
        const float4* bsrc  = (const float4*)(g_Bv + (b * NN + i0) * HH);
        const float4* ajsrc = (const float4*)(g_A  + (b * NN + j0) * HH);
        const float4* bjsrc = (const float4*)(g_Bv + (b * NN + j0) * HH);
        float4* Ai = (float4*)sm.e.Ai;
        float4* Bi = (float4*)sm.e.Bi;
        float4* Aj = (float4*)sm.e.Aj;
        float4* Bj = (float4*)sm.e.Bj;
        for (int e = tid; e < TI * HH / 4; e += 256) { Ai[e] = asrc[e]; Bi[e] = bsrc[e]; }
        for (int e = tid; e < TJ * HH / 4; e += 256) { Aj[e] = ajsrc[e]; Bj[e] = bjsrc[e]; }
    }
    __syncthreads();

    int i = i0 + mg;
    const float* baseb = base + b * NN * NN;
    const float* compb = comp + b * NN * NN;

    float ai[8], biv[8];
    {
        const float* p = sm.e.Ai + mg * HH + hg * 4;
        float4 l = *(const float4*)p;
        float4 u = *(const float4*)(p + 64);
        ai[0]=l.x; ai[1]=l.y; ai[2]=l.z; ai[3]=l.w;
        ai[4]=u.x; ai[5]=u.y; ai[6]=u.z; ai[7]=u.w;
        const float* q = sm.e.Bi + mg * HH + hg * 4;
        float4 l2 = *(const float4*)q;
        float4 u2 = *(const float4*)(q + 64);
        biv[0]=l2.x; biv[1]=l2.y; biv[2]=l2.z; biv[3]=l2.w;
        biv[4]=u2.x; biv[5]=u2.y; biv[6]=u2.z; biv[7]=u2.w;
    }

#pragma unroll
    for (int pp = 0; pp < 4; pp++) {
        float Clo[8], Chi[8];
#pragma unroll
        for (int h = 0; h < 8; h++) unpack2(acc[pp][h], Clo[h], Chi[h]);
#pragma unroll
        for (int lane = 0; lane < 2; lane++) {
            int jj = pp * 2 + lane;
            int j = j0 + jj;

            float bij = clip20(baseb[i * NN + j]);
            float sbij = sigm(bij);
            float cij = clip20(compb[i * NN + j]);
            float scij = sigm(cij);
            float bji = clip20(baseb[j * NN + i]);
            float sbji = sigm(bji);
            float cji = clip20(compb[j * NN + i]);
            float scji = sigm(cji);

            float pA = 0.f, pB = 0.f;
#pragma unroll
            for (int l = 0; l < 8; l++) {
                float Cv = lane ? Chi[l] : Clo[l];
                int hl = (l < 4) ? (hg * 4 + l) : (64 + hg * 4 + (l - 4));
                float ws0 = Wsc[0 * HH + hl];
                float ws1 = Wsc[1 * HH + hl];
                float ws2 = Wsc[2 * HH + hl];
                float ws3 = Wsc[3 * HH + hl];
                float w2v = W2s[hl];
                float ajv = sm.e.Aj[jj * HH + hl];
                float bjv = sm.e.Bj[jj * HH + hl];
                float s1 = bij * ws0 + sbij * ws1 + cij * ws2 + scij * ws3;
                float s2 = bji * ws0 + sbji * ws1 + cji * ws2 + scji * ws3;
                float hA = Cv + ai[l] + bjv + s1;    // hdn(i,j)
                float hB = Cv + ajv + biv[l] + s2;   // hdn(j,i)
                pA += fmaxf(hA, 0.f) * w2v;
                pB += fmaxf(hB, 0.f) * w2v;
            }
            sm.e.red[(mg * 8 + jj) * 16 + hg]       = pA;
            sm.e.red[(128 + mg * 8 + jj) * 16 + hg] = pB;
        }
    }
    __syncthreads();

    if (tid < 128) {
        const float* r0p = sm.e.red + tid * 16;
        const float* r1p = sm.e.red + (128 + tid) * 16;
        float s = 0.f;
#pragma unroll
        for (int g = 0; g < 16; g++) s += r0p[g] + r1p[g];
        float v = 0.5f * s + b2[0];
        int ii = tid >> 3, jj = tid & 7;
        int gi = i0 + ii, gj = j0 + jj;
        float* ob = out + b * NN * NN;
        if (gj > gi) {
            ob[gi * NN + gj] = v;
            ob[gj * NN + gi] = v;
        } else if (gj == gi) {
            ob[gi * NN + gi] = -1e9f;
        }
    }
}

extern "C" void kernel_launch(void* const* d_in, const int* in_sizes, int n_in,
                              void* d_out, int out_size) {
    const float* X    = (const float*)d_in[0];  // node_latents [4,256,128]
    const float* base = (const float*)d_in[1];  // base_edge_logits [4,256,256]
    const float* comp = (const float*)d_in[2];  // completion_logits [4,256,256]
    const float* W1   = (const float*)d_in[3];  // [516,128]
    const float* b1   = (const float*)d_in[4];  // [128]
    const float* W2   = (const float*)d_in[5];  // [128,1]
    const float* b2   = (const float*)d_in[6];  // [1]
    float* out = (float*)d_out;                 // [4,256,256]

    precompute_ab<<<NB * NN / 8, 128>>>(X, W1, b1);
    dim3 grid(NN / TJ, NN / TI, NB);
    pair_mlp_kernel<<<grid, 256>>>(X, base, comp, W1, W2, b2, out);
}

// round 3
// speedup vs baseline: 1.2565x; 1.2565x over previous
#include <cuda_runtime.h>

typedef unsigned long long ull;

#define NB 4
#define NN 256
#define DD 128
#define HH 128
#define TT 8      // 8x8 pair tile
#define KC 32     // k-chunk for W1 staging

// Per-node halves of the first linear layer.
// g_A[b*N+i, h]  = b1[h] + sum_k x[i,k]*W1[k,h]
// g_Bv[b*N+j, h] =         sum_k x[j,k]*W1[128+k,h]
__device__ float g_A[NB * NN * HH];
__device__ float g_Bv[NB * NN * HH];

// ---------- f32x2 helpers ----------
__device__ __forceinline__ ull pack2(float lo, float hi) {
    ull r; asm("mov.b64 %0, {%1,%2};" : "=l"(r) : "f"(lo), "f"(hi)); return r;
}
__device__ __forceinline__ ull dup2(float x) { return pack2(x, x); }
__device__ __forceinline__ void unpack2(ull v, float& lo, float& hi) {
    asm("mov.b64 {%0,%1}, %2;" : "=f"(lo), "=f"(hi) : "l"(v));
}
__device__ __forceinline__ ull ffma2(ull a, ull b, ull c) {
    ull d; asm("fma.rn.f32x2 %0, %1, %2, %3;" : "=l"(d) : "l"(a), "l"(b), "l"(c)); return d;
}
__device__ __forceinline__ ull fmul2(ull a, ull b) {
    ull d; asm("mul.rn.f32x2 %0, %1, %2;" : "=l"(d) : "l"(a), "l"(b)); return d;
}
__device__ __forceinline__ ull fadd2(ull a, ull b) {
    ull d; asm("add.rn.f32x2 %0, %1, %2;" : "=l"(d) : "l"(a), "l"(b)); return d;
}

__device__ __forceinline__ float clip20(float x) { return fminf(fmaxf(x, -20.0f), 20.0f); }
__device__ __forceinline__ float sigm(float x)  { return 1.0f / (1.0f + __expf(-x)); }

// ---------- cp.async helpers ----------
__device__ __forceinline__ void cpasync16(void* dst_smem, const void* src) {
    unsigned d = (unsigned)__cvta_generic_to_shared(dst_smem);
    asm volatile("cp.async.cg.shared.global [%0], [%1], 16;\n" :: "r"(d), "l"(src));
}
__device__ __forceinline__ void cp_commit() { asm volatile("cp.async.commit_group;\n"); }
__device__ __forceinline__ void cp_wait0()  { asm volatile("cp.async.wait_group 0;\n"); }

// ---------- Kernel 1: per-node precompute ----------
__global__ void precompute_ab(const float* __restrict__ X,
                              const float* __restrict__ W1,
                              const float* __restrict__ b1) {
    __shared__ float Xs[8 * DD];
    int r0 = blockIdx.x * 8;
    int h  = threadIdx.x;

    for (int e = h; e < 8 * DD / 4; e += 128)
        ((float4*)Xs)[e] = ((const float4*)(X + r0 * DD))[e];
    __syncthreads();

    float accA[8], accB[8];
#pragma unroll
    for (int r = 0; r < 8; r++) { accA[r] = 0.f; accB[r] = 0.f; }

    for (int k = 0; k < DD; k++) {
        float wa = W1[k * HH + h];
        float wb = W1[(DD + k) * HH + h];
#pragma unroll
        for (int r = 0; r < 8; r++) {
            float x = Xs[r * DD + k];
            accA[r] += x * wa;
            accB[r] += x * wb;
        }
    }
    float bb = b1[h];
#pragma unroll
    for (int r = 0; r < 8; r++) {
        g_A[(r0 + r) * HH + h]  = accA[r] + bb;
        g_Bv[(r0 + r) * HH + h] = accB[r];
    }
}

// ---------- Kernel 2: fused pairwise MLP ----------
struct SmemMain {
    float his[TT * DD];   // 8 i-rows
    float hjT[DD * TT];   // 8 j-rows transposed [k][jj]
    float Wc[KC * HH];    // |hi-hj| weight chunk
    float Wd[KC * HH];    // hi*hj   weight chunk
};
struct SmemEpi {
    float Ai[TT * HH];
    float Bi[TT * HH];
    float Aj[TT * HH];
    float Bj[TT * HH];
    float red[2 * TT * TT * 16];
};
union SmemU { SmemMain m; SmemEpi e; };

__global__ void __launch_bounds__(256, 2)
pair_mlp_kernel(const float* __restrict__ X,
                const float* __restrict__ base,
                const float* __restrict__ comp,
                const float* __restrict__ W1,
                const float* __restrict__ W2,
                const float* __restrict__ b2,
                float* __restrict__ out) {
    int jt = blockIdx.x, it = blockIdx.y, b = blockIdx.z;
    if (jt < it) return;   // lower-triangle tile: partner covers it
    int i0 = it * TT, j0 = jt * TT;
    int tid = threadIdx.x;
    int hg = tid & 15;          // 16 h-groups: h in {hg*4..+3} U {64+hg*4..+3}
    int ii = (tid >> 4) & 7;    // i-row within tile
    int jhalf = tid >> 7;       // jj in [jhalf*4, jhalf*4+4)

    __shared__ __align__(16) SmemU sm;
    __shared__ __align__(16) float Wsc[4 * HH];  // W1 rows 512..515
    __shared__ __align__(16) float W2s[HH];

    const float* Xb = X + b * NN * DD;

    // ---- stage: his, hjT, scalar weights, W2, chunk 0 of Wc/Wd ----
    {
        for (int e = tid; e < TT * DD / 4; e += 256)
            ((float4*)sm.m.his)[e] = ((const float4*)(Xb + i0 * DD))[e];

        for (int e = tid; e < TT * DD / 4; e += 256) {
            int jj = e >> 5;
            int k  = (e & 31) * 4;
            float4 v = *(const float4*)(Xb + (j0 + jj) * DD + k);
            sm.m.hjT[(k + 0) * TT + jj] = v.x;
            sm.m.hjT[(k + 1) * TT + jj] = v.y;
            sm.m.hjT[(k + 2) * TT + jj] = v.z;
            sm.m.hjT[(k + 3) * TT + jj] = v.w;
        }
        for (int e = tid; e < 4 * HH / 4; e += 256)
            ((float4*)Wsc)[e] = ((const float4*)(W1 + 512 * HH))[e];
        if (tid < HH / 4) ((float4*)W2s)[tid] = ((const float4*)W2)[tid];

        // chunk 0 via cp.async
        for (int e = tid; e < KC * HH / 4; e += 256) {
            cpasync16((float4*)sm.m.Wc + e, (const float4*)(W1 + 256 * HH) + e);
            cpasync16((float4*)sm.m.Wd + e, (const float4*)(W1 + 384 * HH) + e);
        }
        cp_commit();
        cp_wait0();
    }
    __syncthreads();

    const ull SGN = 0x8000000080000000ULL;
    const ull ABSM = 0x7FFFFFFF7FFFFFFFULL;

    // acc[pp][h] : f32x2 over jj-pair (jhalf*4 + 2pp, +1)
    ull acc[2][8];
#pragma unroll
    for (int p = 0; p < 2; p++)
#pragma unroll
        for (int h = 0; h < 8; h++) acc[p][h] = 0ULL;

    const float* hisP = sm.m.his + ii * DD;

    for (int c = 0; c < DD / KC; c++) {
#pragma unroll 8
        for (int kk = 0; kk < KC; kk++) {
            int k = c * KC + kk;
            ull hi2 = dup2(hisP[k]);
            ulonglong2 hv = *(const ulonglong2*)(sm.m.hjT + k * TT + jhalf * 4);
            ull hj2[2] = { hv.x, hv.y };
            ull p2[2], a2[2];
#pragma unroll
            for (int pp = 0; pp < 2; pp++) {
                p2[pp] = fmul2(hi2, hj2[pp]);                  // hi*hj
                ull d2 = fadd2(hi2, hj2[pp] ^ SGN);            // hi-hj
                a2[pp] = d2 & ABSM;                            // |hi-hj|
            }
            const float* wcp = sm.m.Wc + kk * HH + hg * 4;
            const float* wdp = sm.m.Wd + kk * HH + hg * 4;
            float4 wcl = *(const float4*)wcp;
            float4 wcu = *(const float4*)(wcp + 64);
            float4 wdl = *(const float4*)wdp;
            float4 wdu = *(const float4*)(wdp + 64);
            float wc[8] = { wcl.x, wcl.y, wcl.z, wcl.w, wcu.x, wcu.y, wcu.z, wcu.w };
            float wd[8] = { wdl.x, wdl.y, wdl.z, wdl.w, wdu.x, wdu.y, wdu.z, wdu.w };
#pragma unroll
            for (int h = 0; h < 8; h++) {
                ull wc2 = dup2(wc[h]);
                ull wd2 = dup2(wd[h]);
#pragma unroll
                for (int pp = 0; pp < 2; pp++) {
                    acc[pp][h] = ffma2(a2[pp], wc2, acc[pp][h]);
                    acc[pp][h] = ffma2(p2[pp], wd2, acc[pp][h]);
                }
            }
        }
        if (c + 1 < DD / KC) {
            __syncthreads();   // all warps done reading current chunk
            for (int e = tid; e < KC * HH / 4; e += 256) {
                cpasync16((float4*)sm.m.Wc + e,
                          (const float4*)(W1 + (256 + (c + 1) * KC) * HH) + e);
                cpasync16((float4*)sm.m.Wd + e,
                          (const float4*)(W1 + (384 + (c + 1) * KC) * HH) + e);
            }
            cp_commit();
            cp_wait0();
            __syncthreads();   // new chunk visible
        }
    }
    __syncthreads();

    // ---- epilogue: stage per-node A/B rows (union overlay safe post-sync) ----
    {
        const float4* asrc  = (const float4*)(g_A  + (b * NN + i0) * HH);
        const float4* bsrc  = (const float4*)(g_Bv + (b * NN + i0) * HH);
        const float4* ajsrc = (const float4*)(g_A  + (b * NN + j0) * HH);
        const float4* bjsrc = (const float4*)(g_Bv + (b * NN + j0) * HH);
        for (int e = tid; e < TT * HH / 4; e += 256) {
            ((float4*)sm.e.Ai)[e] = asrc[e];
            ((float4*)sm.e.Bi)[e] = bsrc[e];
            ((float4*)sm.e.Aj)[e] = ajsrc[e];
            ((float4*)sm.e.Bj)[e] = bjsrc[e];
        }
    }
    __syncthreads();

    int i = i0 + ii;
    const float* baseb = base + b * NN * NN;
    const float* compb = comp + b * NN * NN;

    float ai[8], biv[8];
    {
        const float* p = sm.e.Ai + ii * HH + hg * 4;
        float4 l = *(const float4*)p;
        float4 u = *(const float4*)(p + 64);
        ai[0]=l.x; ai[1]=l.y; ai[2]=l.z; ai[3]=l.w;
        ai[4]=u.x; ai[5]=u.y; ai[6]=u.z; ai[7]=u.w;
        const float* q = sm.e.Bi + ii * HH + hg * 4;
        float4 l2 = *(const float4*)q;
        float4 u2 = *(const float4*)(q + 64);
        biv[0]=l2.x; biv[1]=l2.y; biv[2]=l2.z; biv[3]=l2.w;
        biv[4]=u2.x; biv[5]=u2.y; biv[6]=u2.z; biv[7]=u2.w;
    }

#pragma unroll
    for (int pp = 0; pp < 2; pp++) {
        float Clo[8], Chi[8];
#pragma unroll
        for (int h = 0; h < 8; h++) unpack2(acc[pp][h], Clo[h], Chi[h]);
#pragma unroll
        for (int lane = 0; lane < 2; lane++) {
            int jj = jhalf * 4 + pp * 2 + lane;
            int j = j0 + jj;

            float bij = clip20(baseb[i * NN + j]);
            float sbij = sigm(bij);
            float cij = clip20(compb[i * NN + j]);
            float scij = sigm(cij);
            float bji = clip20(baseb[j * NN + i]);
            float sbji = sigm(bji);
            float cji = clip20(compb[j * NN + i]);
            float scji = sigm(cji);

            float pA = 0.f, pB = 0.f;
#pragma unroll
            for (int l = 0; l < 8; l++) {
                float Cv = lane ? Chi[l] : Clo[l];
                int hl = (l < 4) ? (hg * 4 + l) : (64 + hg * 4 + (l - 4));
                float ws0 = Wsc[0 * HH + hl];
                float ws1 = Wsc[1 * HH + hl];
                float ws2 = Wsc[2 * HH + hl];
                float ws3 = Wsc[3 * HH + hl];
                float w2v = W2s[hl];
                float ajv = sm.e.Aj[jj * HH + hl];
                float bjv = sm.e.Bj[jj * HH + hl];
                float s1 = bij * ws0 + sbij * ws1 + cij * ws2 + scij * ws3;
                float s2 = bji * ws0 + sbji * ws1 + cji * ws2 + scji * ws3;
                float hA = Cv + ai[l] + bjv + s1;    // hdn(i,j)
                float hB = Cv + ajv + biv[l] + s2;   // hdn(j,i)
                pA += fmaxf(hA, 0.f) * w2v;
                pB += fmaxf(hB, 0.f) * w2v;
            }
            sm.e.red[(ii * 8 + jj) * 16 + hg]       = pA;
            sm.e.red[(64 + ii * 8 + jj) * 16 + hg]  = pB;
        }
    }
    __syncthreads();

    if (tid < 64) {
        const float* r0p = sm.e.red + tid * 16;
        const float* r1p = sm.e.red + (64 + tid) * 16;
        float s = 0.f;
#pragma unroll
        for (int g = 0; g < 16; g++) s += r0p[g] + r1p[g];
        float v = 0.5f * s + b2[0];
        int pii = tid >> 3, pjj = tid & 7;
        int gi = i0 + pii, gj = j0 + pjj;
        float* ob = out + b * NN * NN;
        if (gj > gi) {
            ob[gi * NN + gj] = v;
            ob[gj * NN + gi] = v;
        } else if (gj == gi) {
            ob[gi * NN + gi] = -1e9f;
        }
        // gj < gi (diag tiles only): partner thread writes it
    }
}

extern "C" void kernel_launch(void* const* d_in, const int* in_sizes, int n_in,
                              void* d_out, int out_size) {
    const float* X    = (const float*)d_in[0];  // node_latents [4,256,128]
    const float* base = (const float*)d_in[1];  // base_edge_logits [4,256,256]
    const float* comp = (const float*)d_in[2];  // completion_logits [4,256,256]
    const float* W1   = (const float*)d_in[3];  // [516,128]
    const float* b1   = (const float*)d_in[4];  // [128]
    const float* W2   = (const float*)d_in[5];  // [128,1]
    const float* b2   = (const float*)d_in[6];  // [1]
    float* out = (float*)d_out;                 // [4,256,256]

    precompute_ab<<<NB * NN / 8, 128>>>(X, W1, b1);
    dim3 grid(NN / TT, NN / TT, NB);
    pair_mlp_kernel<<<grid, 256>>>(X, base, comp, W1, W2, b2, out);
}